// round 4
// baseline (speedup 1.0000x reference)
#include <cuda_runtime.h>
#include <cuda_bf16.h>

// Blockwise 256-point regular Hadamard transform (H = kron(H4 x4) / 16).
// out[..., b*256 + :] = H @ x[..., b*256 + :]
//
// Implemented as a fast transform: 4 radix-4 butterfly stages at strides
// 1, 4, 16, 64. Per quartet: s = a+b+c+d; y0=s-2d, y1=s-2c, y2=s-2b, y3=s-2a
// (rows of H4 = [[1,1,1,-1],[1,1,-1,1],[1,-1,1,1],[-1,1,1,1]]).
// Final 1/16 scale folded into the last stage.
//
// Layout: 256 threads/CTA, 16 Hadamard blocks (4096 floats) per CTA.
// Thread (h = tid>>4, j = tid&15) loads 16 consecutive floats (digits d0,d1),
// does stages 0-1 in registers, transposes through SMEM (row stride 17,
// block stride 272 -> all four scalar access phases are bank-conflict-free),
// does stages 2-3 (digits d2,d3) in registers, transposes back, and stores
// 4x float4 fully coalesced.

#define BF4(a,b,c,d)                                   \
    do {                                               \
        float _s = ((a)+(b)) + ((c)+(d));              \
        float _ta=(a), _tb=(b), _tc=(c);               \
        (a) = fmaf(-2.0f, (d), _s);                    \
        (b) = fmaf(-2.0f, _tc, _s);                    \
        (c) = fmaf(-2.0f, _tb, _s);                    \
        (d) = fmaf(-2.0f, _ta, _s);                    \
    } while (0)

// Last stage: fold the 1/16 scale in. y/16 = fma(-2/16, x, s/16).
#define BF4S(a,b,c,d)                                  \
    do {                                               \
        float _s = (((a)+(b)) + ((c)+(d))) * 0.0625f;  \
        float _ta=(a), _tb=(b), _tc=(c);               \
        (a) = fmaf(-0.125f, (d), _s);                  \
        (b) = fmaf(-0.125f, _tc, _s);                  \
        (c) = fmaf(-0.125f, _tb, _s);                  \
        (d) = fmaf(-0.125f, _ta, _s);                  \
    } while (0)

__global__ __launch_bounds__(256) void had256_kernel(
    const float* __restrict__ x, float* __restrict__ y)
{
    __shared__ float smA[16 * 272];
    __shared__ float smB[16 * 272];

    const int tid = threadIdx.x;
    const int h   = tid >> 4;   // hadamard block within CTA [0,16)
    const int j   = tid & 15;   // 16-float chunk within block [0,16)
    const int sb  = h * 272;    // smem base for this block (272 mod 32 == 16)

    const size_t gbase = ((size_t)blockIdx.x << 12) + ((size_t)h << 8) + ((size_t)j << 4);

    // ---- load 16 consecutive floats: element e = j*16 + i, i = d1*4 + d0 ----
    const float4* xin = reinterpret_cast<const float4*>(x + gbase);
    float v[16];
    {
        float4 p;
        p = __ldcs(xin + 0); v[0]=p.x;  v[1]=p.y;  v[2]=p.z;  v[3]=p.w;
        p = __ldcs(xin + 1); v[4]=p.x;  v[5]=p.y;  v[6]=p.z;  v[7]=p.w;
        p = __ldcs(xin + 2); v[8]=p.x;  v[9]=p.y;  v[10]=p.z; v[11]=p.w;
        p = __ldcs(xin + 3); v[12]=p.x; v[13]=p.y; v[14]=p.z; v[15]=p.w;
    }

    // ---- stage 0 (digit d0, stride 1) ----
    BF4(v[0], v[1], v[2],  v[3]);
    BF4(v[4], v[5], v[6],  v[7]);
    BF4(v[8], v[9], v[10], v[11]);
    BF4(v[12],v[13],v[14], v[15]);
    // ---- stage 1 (digit d1, stride 4) ----
    BF4(v[0], v[4], v[8],  v[12]);
    BF4(v[1], v[5], v[9],  v[13]);
    BF4(v[2], v[6], v[10], v[14]);
    BF4(v[3], v[7], v[11], v[15]);

    // ---- transpose 1: write rows indexed by i (low digits), col j ----
    // addr = sb + i*17 + j : per fixed i, banks {17i + j + 16*(h&1)} cover all 32.
    #pragma unroll
    for (int i = 0; i < 16; i++)
        smA[sb + i * 17 + j] = v[i];

    __syncthreads();

    // ---- read element e = j + 16k  (row j', col k) ----
    // addr = sb + j*17 + k : per fixed k, banks {17j + k + 16*(h&1)} cover all 32.
    float w[16];
    #pragma unroll
    for (int k = 0; k < 16; k++)
        w[k] = smA[sb + j * 17 + k];

    // ---- stage 2 (digit d2, stride 16) ----
    BF4(w[0], w[1], w[2],  w[3]);
    BF4(w[4], w[5], w[6],  w[7]);
    BF4(w[8], w[9], w[10], w[11]);
    BF4(w[12],w[13],w[14], w[15]);
    // ---- stage 3 (digit d3, stride 64) + 1/16 scale ----
    BF4S(w[0], w[4], w[8],  w[12]);
    BF4S(w[1], w[5], w[9],  w[13]);
    BF4S(w[2], w[6], w[10], w[14]);
    BF4S(w[3], w[7], w[11], w[15]);

    // ---- transpose 2: thread holds e = 16k + j -> write row j, col k ----
    #pragma unroll
    for (int k = 0; k < 16; k++)
        smB[sb + j * 17 + k] = w[k];

    __syncthreads();

    // ---- reader view: element e = j*16 + i lives at row i, col j ----
    float4* yo = reinterpret_cast<float4*>(y + gbase);
    {
        float4 q;
        q.x = smB[sb + 0*17 + j];  q.y = smB[sb + 1*17 + j];
        q.z = smB[sb + 2*17 + j];  q.w = smB[sb + 3*17 + j];
        __stcs(yo + 0, q);
        q.x = smB[sb + 4*17 + j];  q.y = smB[sb + 5*17 + j];
        q.z = smB[sb + 6*17 + j];  q.w = smB[sb + 7*17 + j];
        __stcs(yo + 1, q);
        q.x = smB[sb + 8*17 + j];  q.y = smB[sb + 9*17 + j];
        q.z = smB[sb + 10*17 + j]; q.w = smB[sb + 11*17 + j];
        __stcs(yo + 2, q);
        q.x = smB[sb + 12*17 + j]; q.y = smB[sb + 13*17 + j];
        q.z = smB[sb + 14*17 + j]; q.w = smB[sb + 15*17 + j];
        __stcs(yo + 3, q);
    }
}

extern "C" void kernel_launch(void* const* d_in, const int* in_sizes, int n_in,
                              void* d_out, int out_size)
{
    // Identify x as the largest input (x = 2*4096*8192 floats; H = 256*256).
    // H is not needed: it is the fixed regular Hadamard matrix, applied
    // analytically via the fast transform above.
    int xi = 0;
    long long best = -1;
    for (int i = 0; i < n_in; i++) {
        if ((long long)in_sizes[i] > best) { best = in_sizes[i]; xi = i; }
    }
    const float* x = (const float*)d_in[xi];
    float*       y = (float*)d_out;

    // Each CTA handles 4096 elements (16 Hadamard blocks of 256).
    int nblocks = out_size >> 12;  // out_size = 67108864 -> 16384 CTAs
    had256_kernel<<<nblocks, 256>>>(x, y);
}

// round 5
// speedup vs baseline: 1.0888x; 1.0888x over previous
#include <cuda_runtime.h>
#include <cuda_bf16.h>

// Blockwise 256-point regular Hadamard transform (H = kron(H4 x4) / 16).
// Fast transform: 4 radix-4 stages (strides 1,4,16,64); per quartet
// s = a+b+c+d; y_i = s - 2*x_rev(i). Final 1/16 folded into last stage.
//
// R4 changes vs R2:
//  - The 16 threads of one Hadamard block are consecutive lanes of ONE warp,
//    so both transposes are warp-local: __syncthreads -> __syncwarp.
//  - Single reused smem buffer (transpose-2 writes back to the thread's own
//    row, read only by itself before the sync): 35KB -> 21KB, occ 6->8 CTA/SM.
//  - Row stride 20 floats (80B) + block stride 336 (== 16 mod 32):
//    * scalar column phases: half-warps hit complementary 16-bank sets -> CF
//    * row phases: 16B-aligned, each 8-lane quad of LDS.128/STS.128 covers
//      all 32 banks once (20j mod 32, j=0..7 -> {0,20,8,28,16,4,24,12}) -> CF
//    Shared ops per thread: 16 STS.32 + 4 LDS.128 + 4 STS.128 + 16 LDS.32
//    (was 64 scalar ops).

#define BF4(a,b,c,d)                                   \
    do {                                               \
        float _s = ((a)+(b)) + ((c)+(d));              \
        float _ta=(a), _tb=(b), _tc=(c);               \
        (a) = fmaf(-2.0f, (d), _s);                    \
        (b) = fmaf(-2.0f, _tc, _s);                    \
        (c) = fmaf(-2.0f, _tb, _s);                    \
        (d) = fmaf(-2.0f, _ta, _s);                    \
    } while (0)

// Last stage with folded 1/16 scale: y/16 = fma(-2/16, x, s/16).
#define BF4S(a,b,c,d)                                  \
    do {                                               \
        float _s = (((a)+(b)) + ((c)+(d))) * 0.0625f;  \
        float _ta=(a), _tb=(b), _tc=(c);               \
        (a) = fmaf(-0.125f, (d), _s);                  \
        (b) = fmaf(-0.125f, _tc, _s);                  \
        (c) = fmaf(-0.125f, _tb, _s);                  \
        (d) = fmaf(-0.125f, _ta, _s);                  \
    } while (0)

#define RS 20    // smem row stride in floats (80B, 16B-aligned)
#define SB 336   // smem block stride in floats (336 mod 32 == 16)

__global__ __launch_bounds__(256) void had256_kernel(
    const float* __restrict__ x, float* __restrict__ y)
{
    __shared__ __align__(16) float sm[16 * SB];

    const int tid = threadIdx.x;
    const int h   = tid >> 4;       // hadamard block within CTA [0,16)
    const int j   = tid & 15;       // chunk within block [0,16)
    const int sbase = h * SB;

    const size_t gbase = ((size_t)blockIdx.x << 12) + ((size_t)h << 8) + ((size_t)j << 4);

    // ---- load 16 consecutive floats: e = j*16 + i, i = d1*4 + d0 ----
    const float4* xin = reinterpret_cast<const float4*>(x + gbase);
    float v[16];
    {
        float4 p;
        p = __ldcs(xin + 0); v[0]=p.x;  v[1]=p.y;  v[2]=p.z;  v[3]=p.w;
        p = __ldcs(xin + 1); v[4]=p.x;  v[5]=p.y;  v[6]=p.z;  v[7]=p.w;
        p = __ldcs(xin + 2); v[8]=p.x;  v[9]=p.y;  v[10]=p.z; v[11]=p.w;
        p = __ldcs(xin + 3); v[12]=p.x; v[13]=p.y; v[14]=p.z; v[15]=p.w;
    }

    // ---- stage 0 (d0, stride 1) ----
    BF4(v[0], v[1], v[2],  v[3]);
    BF4(v[4], v[5], v[6],  v[7]);
    BF4(v[8], v[9], v[10], v[11]);
    BF4(v[12],v[13],v[14], v[15]);
    // ---- stage 1 (d1, stride 4) ----
    BF4(v[0], v[4], v[8],  v[12]);
    BF4(v[1], v[5], v[9],  v[13]);
    BF4(v[2], v[6], v[10], v[14]);
    BF4(v[3], v[7], v[11], v[15]);

    // ---- transpose 1: element e = j*16+i -> row i, col j (scalar STS, CF) ----
    #pragma unroll
    for (int i = 0; i < 16; i++)
        sm[sbase + i * RS + j] = v[i];

    __syncwarp();

    // ---- gather row j: w[k] = element k*16 + j  (4x LDS.128, CF) ----
    float w[16];
    {
        const float4* rp = reinterpret_cast<const float4*>(sm + sbase + j * RS);
        float4 a;
        a = rp[0]; w[0]=a.x;  w[1]=a.y;  w[2]=a.z;  w[3]=a.w;
        a = rp[1]; w[4]=a.x;  w[5]=a.y;  w[6]=a.z;  w[7]=a.w;
        a = rp[2]; w[8]=a.x;  w[9]=a.y;  w[10]=a.z; w[11]=a.w;
        a = rp[3]; w[12]=a.x; w[13]=a.y; w[14]=a.z; w[15]=a.w;
    }

    // ---- stage 2 (d2, stride 16) ----
    BF4(w[0], w[1], w[2],  w[3]);
    BF4(w[4], w[5], w[6],  w[7]);
    BF4(w[8], w[9], w[10], w[11]);
    BF4(w[12],w[13],w[14], w[15]);
    // ---- stage 3 (d3, stride 64) + 1/16 scale ----
    BF4S(w[0], w[4], w[8],  w[12]);
    BF4S(w[1], w[5], w[9],  w[13]);
    BF4S(w[2], w[6], w[10], w[14]);
    BF4S(w[3], w[7], w[11], w[15]);

    // ---- transpose 2: write back to OWN row (no cross-thread hazard before
    //      the sync; 4x STS.128, CF). Element 16k+j lands at [row j, col k]. ----
    {
        float4* wp = reinterpret_cast<float4*>(sm + sbase + j * RS);
        wp[0] = make_float4(w[0],  w[1],  w[2],  w[3]);
        wp[1] = make_float4(w[4],  w[5],  w[6],  w[7]);
        wp[2] = make_float4(w[8],  w[9],  w[10], w[11]);
        wp[3] = make_float4(w[12], w[13], w[14], w[15]);
    }

    __syncwarp();

    // ---- gather column j: element e = j*16 + i is at [row i, col j] ----
    float4* yo = reinterpret_cast<float4*>(y + gbase);
    {
        float4 q;
        q.x = sm[sbase + 0*RS + j];  q.y = sm[sbase + 1*RS + j];
        q.z = sm[sbase + 2*RS + j];  q.w = sm[sbase + 3*RS + j];
        __stcs(yo + 0, q);
        q.x = sm[sbase + 4*RS + j];  q.y = sm[sbase + 5*RS + j];
        q.z = sm[sbase + 6*RS + j];  q.w = sm[sbase + 7*RS + j];
        __stcs(yo + 1, q);
        q.x = sm[sbase + 8*RS + j];  q.y = sm[sbase + 9*RS + j];
        q.z = sm[sbase + 10*RS + j]; q.w = sm[sbase + 11*RS + j];
        __stcs(yo + 2, q);
        q.x = sm[sbase + 12*RS + j]; q.y = sm[sbase + 13*RS + j];
        q.z = sm[sbase + 14*RS + j]; q.w = sm[sbase + 15*RS + j];
        __stcs(yo + 3, q);
    }
}

extern "C" void kernel_launch(void* const* d_in, const int* in_sizes, int n_in,
                              void* d_out, int out_size)
{
    // x = largest input; H is the fixed regular Hadamard matrix, applied
    // analytically by the fast transform (never read).
    int xi = 0;
    long long best = -1;
    for (int i = 0; i < n_in; i++) {
        if ((long long)in_sizes[i] > best) { best = in_sizes[i]; xi = i; }
    }
    const float* x = (const float*)d_in[xi];
    float*       y = (float*)d_out;

    // 4096 elements (16 Hadamard blocks) per CTA.
    int nblocks = out_size >> 12;   // 67108864 -> 16384 CTAs
    had256_kernel<<<nblocks, 256>>>(x, y);
}

// round 7
// speedup vs baseline: 1.5546x; 1.4278x over previous
#include <cuda_runtime.h>
#include <cuda_bf16.h>

// Blockwise 256-point regular Hadamard transform (H = kron(H4 x4) / 16).
// Fast transform, 4 radix-4 stages. KEY: the four stages act on independent
// base-4 digits of the element index and therefore COMMUTE. R5 exploits this
// to use a single smem transpose:
//
//   1. vector load 16 consecutive floats  (elements e = 16j + i)
//   2. butterfly digits d0,d1 in registers
//   3. ONE smem transpose (scalar STS columns, vector LDS.128 rows, both
//      bank-conflict-free with row stride 20 / block stride 336)
//   4. thread now holds elements e = 16k + j; butterfly digits d2,d3
//      in registers (register strides 1 and 4)
//   5. scalar STG.32: for fixed k, a warp writes two dense 64B segments
//      (fully sector-coalesced)
//
// Shared traffic halved vs R4 (one transpose instead of two), one syncwarp
// removed. Final 1/16 scale folded into the last stage.

#define BF4(a,b,c,d)                                   \
    do {                                               \
        float _s = ((a)+(b)) + ((c)+(d));              \
        float _ta=(a), _tb=(b), _tc=(c);               \
        (a) = fmaf(-2.0f, (d), _s);                    \
        (b) = fmaf(-2.0f, _tc, _s);                    \
        (c) = fmaf(-2.0f, _tb, _s);                    \
        (d) = fmaf(-2.0f, _ta, _s);                    \
    } while (0)

// Last stage with folded 1/16 scale: y/16 = fma(-2/16, x, s/16).
#define BF4S(a,b,c,d)                                  \
    do {                                               \
        float _s = (((a)+(b)) + ((c)+(d))) * 0.0625f;  \
        float _ta=(a), _tb=(b), _tc=(c);               \
        (a) = fmaf(-0.125f, (d), _s);                  \
        (b) = fmaf(-0.125f, _tc, _s);                  \
        (c) = fmaf(-0.125f, _tb, _s);                  \
        (d) = fmaf(-0.125f, _ta, _s);                  \
    } while (0)

#define RS 20    // smem row stride in floats (80B, 16B-aligned)
#define SB 336   // smem block stride in floats (336 mod 32 == 16)

__global__ __launch_bounds__(256) void had256_kernel(
    const float* __restrict__ x, float* __restrict__ y)
{
    __shared__ __align__(16) float sm[16 * SB];

    const int tid = threadIdx.x;
    const int h   = tid >> 4;        // hadamard block within CTA [0,16)
    const int j   = tid & 15;        // lane within 16-group [0,16)
    const int sbase = h * SB;

    const size_t blk = ((size_t)blockIdx.x << 12) + ((size_t)h << 8);

    // ---- load 16 consecutive floats: e = 16j + i ----
    const float4* xin = reinterpret_cast<const float4*>(x + blk + ((size_t)j << 4));
    float v[16];
    {
        float4 p;
        p = __ldcs(xin + 0); v[0]=p.x;  v[1]=p.y;  v[2]=p.z;  v[3]=p.w;
        p = __ldcs(xin + 1); v[4]=p.x;  v[5]=p.y;  v[6]=p.z;  v[7]=p.w;
        p = __ldcs(xin + 2); v[8]=p.x;  v[9]=p.y;  v[10]=p.z; v[11]=p.w;
        p = __ldcs(xin + 3); v[12]=p.x; v[13]=p.y; v[14]=p.z; v[15]=p.w;
    }

    // ---- stage d0 (element stride 1 = reg stride 1) ----
    BF4(v[0], v[1], v[2],  v[3]);
    BF4(v[4], v[5], v[6],  v[7]);
    BF4(v[8], v[9], v[10], v[11]);
    BF4(v[12],v[13],v[14], v[15]);
    // ---- stage d1 (element stride 4 = reg stride 4) ----
    BF4(v[0], v[4], v[8],  v[12]);
    BF4(v[1], v[5], v[9],  v[13]);
    BF4(v[2], v[6], v[10], v[14]);
    BF4(v[3], v[7], v[11], v[15]);

    // ---- single transpose: element 16j+i -> row i, col j ----
    // scalar STS: fixed i, lanes cover all 32 banks (two 16-bank halves). CF.
    #pragma unroll
    for (int i = 0; i < 16; i++)
        sm[sbase + i * RS + j] = v[i];

    __syncwarp();

    // vector LDS: thread j reads row j -> w[k] = element 16k + j.
    // 20j mod 32 distinct per 8-lane phase -> CF.
    float w[16];
    {
        const float4* rp = reinterpret_cast<const float4*>(sm + sbase + j * RS);
        float4 a;
        a = rp[0]; w[0]=a.x;  w[1]=a.y;  w[2]=a.z;  w[3]=a.w;
        a = rp[1]; w[4]=a.x;  w[5]=a.y;  w[6]=a.z;  w[7]=a.w;
        a = rp[2]; w[8]=a.x;  w[9]=a.y;  w[10]=a.z; w[11]=a.w;
        a = rp[3]; w[12]=a.x; w[13]=a.y; w[14]=a.z; w[15]=a.w;
    }

    // ---- stage d2 (element stride 16 = reg stride 1) ----
    BF4(w[0], w[1], w[2],  w[3]);
    BF4(w[4], w[5], w[6],  w[7]);
    BF4(w[8], w[9], w[10], w[11]);
    BF4(w[12],w[13],w[14], w[15]);
    // ---- stage d3 (element stride 64 = reg stride 4) + 1/16 scale ----
    BF4S(w[0], w[4], w[8],  w[12]);
    BF4S(w[1], w[5], w[9],  w[13]);
    BF4S(w[2], w[6], w[10], w[14]);
    BF4S(w[3], w[7], w[11], w[15]);

    // ---- scalar store: w[k] -> y[blk + 16k + j] ----
    // Per instr (fixed k) a warp writes two dense 64B segments: coalesced.
    float* yo = y + blk + j;
    #pragma unroll
    for (int k = 0; k < 16; k++)
        __stcs(yo + (k << 4), w[k]);
}

extern "C" void kernel_launch(void* const* d_in, const int* in_sizes, int n_in,
                              void* d_out, int out_size)
{
    // x = largest input; H is the fixed regular Hadamard matrix, applied
    // analytically by the fast transform (never read).
    int xi = 0;
    long long best = -1;
    for (int i = 0; i < n_in; i++) {
        if ((long long)in_sizes[i] > best) { best = in_sizes[i]; xi = i; }
    }
    const float* x = (const float*)d_in[xi];
    float*       y = (float*)d_out;

    // 4096 elements (16 Hadamard blocks) per CTA.
    int nblocks = out_size >> 12;   // 67108864 -> 16384 CTAs
    had256_kernel<<<nblocks, 256>>>(x, y);
}